// round 8
// baseline (speedup 1.0000x reference)
#include <cuda_runtime.h>
#include <cuda_bf16.h>
#include <math.h>

#define NN 100000
#define NE 1000000
#define D  64
#define H  128
#define NG 64
#define CAT 160
#define SCAN_BLK 1024
#define SCAN_NB  98            // 98*1024 >= NN

typedef unsigned long long u64;

// ---------------- f32x2 packed-math helpers ----------------
__device__ __forceinline__ void ffma2(u64& d, u64 a, u64 b) {
    asm("fma.rn.f32x2 %0, %1, %2, %0;" : "+l"(d) : "l"(a), "l"(b));
}
__device__ __forceinline__ u64 pack2(float lo, float hi) {
    u64 r; asm("mov.b64 %0, {%1, %2};" : "=l"(r) : "f"(lo), "f"(hi)); return r;
}
__device__ __forceinline__ float2 unpack2(u64 v) {
    float2 f; asm("mov.b64 {%0, %1}, %2;" : "=f"(f.x), "=f"(f.y) : "l"(v)); return f;
}

// ---------------- scratch (device globals: no runtime alloc) ----------------
__device__ float g_h[NN * D];
__device__ float g_AB[(size_t)NN * 2 * H];   // [n][0:128]=h@W1a, [128:256]=h@W1b
__device__ float g_aggY[(size_t)NN * H];
__device__ int   g_degi[NN];
__device__ float g_deg[NN];
__device__ int   g_off[NN];
__device__ int   g_fill[NN];
__device__ int   g_bsum[SCAN_NB];
__device__ int   g_bsumx[SCAN_NB];
__device__ int   g_esrc[NE];                 // dst-sorted: src per slot
__device__ int   g_edst[NE];                 // dst per slot (non-decreasing)
__device__ float g_ed[NE];                   // dist, kind packed in sign bit
__device__ float g_ktab4[4 * 2 * H];
__device__ float g_pool[NG * D];
__device__ float g_cnt[NG];

__device__ __forceinline__ void red_add_v4(float* p, float4 v) {
    asm volatile("red.global.add.v4.f32 [%0], {%1,%2,%3,%4};"
                 :: "l"(p), "f"(v.x), "f"(v.y), "f"(v.z), "f"(v.w) : "memory");
}

// ---------------- init: node embedding gather ----------------
__global__ void k_embed(const int* __restrict__ atoms, const float* __restrict__ emb) {
    int i = blockIdx.x * blockDim.x + threadIdx.x;
    if (i >= NN * (D / 4)) return;
    int n = i >> 4, q = i & 15;
    int a = atoms[n];
    reinterpret_cast<float4*>(g_h)[i] = reinterpret_cast<const float4*>(emb)[a * (D / 4) + q];
}

// ---------------- CSR build (edge sort by dst) ----------------
__global__ void k_zero_int() {
    int i = blockIdx.x * blockDim.x + threadIdx.x;
    if (i < NN) { g_degi[i] = 0; g_fill[i] = 0; }
}
__global__ void k_count(const int* __restrict__ ei) {
    int e = blockIdx.x * blockDim.x + threadIdx.x;
    if (e < NE) atomicAdd(&g_degi[ei[NE + e]], 1);
}
__global__ void __launch_bounds__(SCAN_BLK) k_scanA() {
    __shared__ int sm[SCAN_BLK];
    int t = threadIdx.x;
    int idx = blockIdx.x * SCAN_BLK + t;
    int v = (idx < NN) ? g_degi[idx] : 0;
    sm[t] = v; __syncthreads();
#pragma unroll
    for (int ofs = 1; ofs < SCAN_BLK; ofs <<= 1) {
        int add = (t >= ofs) ? sm[t - ofs] : 0;
        __syncthreads();
        sm[t] += add;
        __syncthreads();
    }
    if (idx < NN) g_off[idx] = sm[t] - v;
    if (t == SCAN_BLK - 1) g_bsum[blockIdx.x] = sm[t];
}
__global__ void k_scanB() {
    if (threadIdx.x == 0) {
        int run = 0;
        for (int b = 0; b < SCAN_NB; b++) { g_bsumx[b] = run; run += g_bsum[b]; }
    }
}
__global__ void k_scanC() {
    int i = blockIdx.x * blockDim.x + threadIdx.x;
    if (i < NN) {
        g_off[i] += g_bsumx[i >> 10];
        g_deg[i] = (float)g_degi[i];
    }
}
__global__ void k_scatter(const int* __restrict__ ei, const float* __restrict__ coord,
                          const int* __restrict__ isr) {
    int e = blockIdx.x * blockDim.x + threadIdx.x;
    if (e >= NE) return;
    int s = ei[e], d = ei[NE + e];
    float dx = coord[3 * s + 0] - coord[3 * d + 0];
    float dy = coord[3 * s + 1] - coord[3 * d + 1];
    float dz = coord[3 * s + 2] - coord[3 * d + 2];
    float dist = sqrtf(dx * dx + dy * dy + dz * dz);
    int kind = (isr[s] != isr[d]) ? 1 : 0;
    int pos = g_off[d] + atomicAdd(&g_fill[d], 1);
    g_esrc[pos] = s;
    g_edst[pos] = d;
    g_ed[pos] = kind ? -dist : dist;
}

// ---------------- ktab for all layers ----------------
__global__ void k_ktab_all(const float* __restrict__ W1, const float* __restrict__ b1,
                           const float* __restrict__ su) {
    int l = blockIdx.x;
    int j = threadIdx.x;
    const float* W1l = W1 + (size_t)l * CAT * H;
    for (int kd = 0; kd < 2; kd++) {
        float s = b1[l * H + j];
#pragma unroll
        for (int g = 0; g < 16; g++) s += su[kd * 16 + g] * W1l[(144 + g) * H + j];
        g_ktab4[(l * 2 + kd) * H + j] = s;
    }
}

// ---------------- per layer: AB[n][0:256] = h[n] @ [W1a | W1b] (f32x2 packed) ----------------
// smem weights stored k-pair interleaved: pos(k,col) = (k>>1)*512 + col*2 + (k&1)
__global__ void __launch_bounds__(256) k_nodeproj(const float* __restrict__ W1l) {
    extern __shared__ float sm[];
    float* sW = sm;               // 32*512 = 16384 floats (interleaved k-pairs)
    float* sh = sm + 16384;       // [32][64]
    int t = threadIdx.x;
    int n0 = blockIdx.x * 32;

    for (int idx = t; idx < 64 * 256; idx += 256) {
        int k = idx >> 8, j = idx & 255;
        float val = (j < H) ? W1l[k * H + j] : W1l[(64 + k) * H + (j - H)];
        sW[(k >> 1) * 512 + j * 2 + (k & 1)] = val;
    }
    for (int idx = t; idx < 32 * 16; idx += 256) {
        int r = idx >> 4, q = idx & 15;
        reinterpret_cast<float4*>(sh + r * 64)[q] =
            *reinterpret_cast<const float4*>(g_h + (size_t)(n0 + r) * D + 4 * q);
    }
    __syncthreads();

    int cg = t & 63;        // 4-col group of 256
    int ng = t >> 6;        // rows ng + 4*i
    u64 acc2[8][4];
#pragma unroll
    for (int i = 0; i < 8; i++)
#pragma unroll
        for (int q = 0; q < 4; q++) acc2[i][q] = 0ULL;

    for (int k2 = 0; k2 < 32; k2 += 2) {
        const ulonglong2* wpa = reinterpret_cast<const ulonglong2*>(sW + (k2 + 0) * 512) + 2 * cg;
        const ulonglong2* wpb = reinterpret_cast<const ulonglong2*>(sW + (k2 + 1) * 512) + 2 * cg;
        ulonglong2 wa0 = wpa[0], wa1 = wpa[1];
        ulonglong2 wb0 = wpb[0], wb1 = wpb[1];
#pragma unroll
        for (int i = 0; i < 8; i++) {
            ulonglong2 hp = *reinterpret_cast<const ulonglong2*>(sh + (ng + 4 * i) * 64 + 2 * k2);
            ffma2(acc2[i][0], wa0.x, hp.x);
            ffma2(acc2[i][1], wa0.y, hp.x);
            ffma2(acc2[i][2], wa1.x, hp.x);
            ffma2(acc2[i][3], wa1.y, hp.x);
            ffma2(acc2[i][0], wb0.x, hp.y);
            ffma2(acc2[i][1], wb0.y, hp.y);
            ffma2(acc2[i][2], wb1.x, hp.y);
            ffma2(acc2[i][3], wb1.y, hp.y);
        }
    }
#pragma unroll
    for (int i = 0; i < 8; i++) {
        int n = n0 + ng + 4 * i;
        float2 f0 = unpack2(acc2[i][0]);
        float2 f1 = unpack2(acc2[i][1]);
        float2 f2 = unpack2(acc2[i][2]);
        float2 f3 = unpack2(acc2[i][3]);
        float4 o = make_float4(f0.x + f0.y, f1.x + f1.y, f2.x + f2.y, f3.x + f3.y);
        reinterpret_cast<float4*>(g_AB + (size_t)n * 256)[cg] = o;
    }
}

// ---------------- zero helpers ----------------
__global__ void k_zeroY() {
    int i = blockIdx.x * blockDim.x + threadIdx.x;
    if (i < NN * (H / 4)) reinterpret_cast<float4*>(g_aggY)[i] = make_float4(0.f, 0.f, 0.f, 0.f);
}
__global__ void k_zero_pool() {
    int i = threadIdx.x;
    if (i < NG * (D / 4)) reinterpret_cast<float4*>(g_pool)[i] = make_float4(0.f, 0.f, 0.f, 0.f);
    if (i < NG) g_cnt[i] = 0.f;
}

// ---------------- edge kernel: dst-sorted slots, segmented accumulation, f32x2 rbf loop ----------------
__global__ void __launch_bounds__(256, 2)
k_edge(const float* __restrict__ W1l, int l) {
    int lane = threadIdx.x & 31;
    int warp = threadIdx.x >> 5;
    int e0 = (blockIdx.x * 8 + warp) * 8;   // 8 slots per warp; NE = 15625*64

    // W1c rows 128..143 packed into gaussian pairs: w1p[g2][c] = {W1c[2g2][c], W1c[2g2+1][c]}
    u64 w1p[8][4];
#pragma unroll
    for (int g2 = 0; g2 < 8; g2++) {
        float4 wa = *reinterpret_cast<const float4*>(W1l + (128 + 2 * g2 + 0) * H + 4 * lane);
        float4 wb = *reinterpret_cast<const float4*>(W1l + (128 + 2 * g2 + 1) * H + 4 * lane);
        w1p[g2][0] = pack2(wa.x, wb.x);
        w1p[g2][1] = pack2(wa.y, wb.y);
        w1p[g2][2] = pack2(wa.z, wb.z);
        w1p[g2][3] = pack2(wa.w, wb.w);
    }
    float4 kt0 = *reinterpret_cast<const float4*>(g_ktab4 + (l * 2 + 0) * H + 4 * lane);
    float4 kt1 = *reinterpret_cast<const float4*>(g_ktab4 + (l * 2 + 1) * H + 4 * lane);

    // coalesced slot metadata
    int m = lane & 7;
    int   sv = g_esrc[e0 + m];
    int   dv = g_edst[e0 + m];
    float ev = g_ed[e0 + m];

    // prefetch slot 0
    int s = __shfl_sync(0xffffffffu, sv, 0);
    int d = __shfl_sync(0xffffffffu, dv, 0);
    float4 b   = *reinterpret_cast<const float4*>(g_AB + (size_t)s * 256 + 128 + 4 * lane);
    float4 abd = *reinterpret_cast<const float4*>(g_AB + (size_t)d * 256 + 4 * lane);

    int cur = d;
    float4 base0 = make_float4(abd.x + kt0.x, abd.y + kt0.y, abd.z + kt0.z, abd.w + kt0.w);
    float4 base1 = make_float4(abd.x + kt1.x, abd.y + kt1.y, abd.z + kt1.z, abd.w + kt1.w);
    float4 acc = make_float4(0.f, 0.f, 0.f, 0.f);

#pragma unroll
    for (int i = 0; i < 8; i++) {
        // prefetch slot i+1
        int sn = 0, dn = 0;
        float4 bn, abdn;
        if (i < 7) {
            sn = __shfl_sync(0xffffffffu, sv, i + 1);
            dn = __shfl_sync(0xffffffffu, dv, i + 1);
            bn = *reinterpret_cast<const float4*>(g_AB + (size_t)sn * 256 + 128 + 4 * lane);
            abdn = (dn != d)
                ? *reinterpret_cast<const float4*>(g_AB + (size_t)dn * 256 + 4 * lane)
                : abd;
        }
        float evi = __shfl_sync(0xffffffffu, ev, i);

        if (d != cur) {
            red_add_v4(g_aggY + (size_t)cur * 128 + 4 * lane, acc);
            acc = make_float4(0.f, 0.f, 0.f, 0.f);
            base0 = make_float4(abd.x + kt0.x, abd.y + kt0.y, abd.z + kt0.z, abd.w + kt0.w);
            base1 = make_float4(abd.x + kt1.x, abd.y + kt1.y, abd.z + kt1.z, abd.w + kt1.w);
            cur = d;
        }

        float dist = fabsf(evi);
        int kd = (__float_as_uint(evi) >> 31);

        float dg = dist - (float)(lane & 15) * (1.0f / 3.0f);
        float rme = __expf(-4.5f * dg * dg);

        // rbf @ W1c with packed gaussian pairs (even-g sums in lo, odd-g in hi)
        u64 z2[4] = {0ULL, 0ULL, 0ULL, 0ULL};
#pragma unroll
        for (int g2 = 0; g2 < 8; g2++) {
            float r0 = __shfl_sync(0xffffffffu, rme, 2 * g2 + 0);
            float r1 = __shfl_sync(0xffffffffu, rme, 2 * g2 + 1);
            u64 rr = pack2(r0, r1);
            ffma2(z2[0], rr, w1p[g2][0]);
            ffma2(z2[1], rr, w1p[g2][1]);
            ffma2(z2[2], rr, w1p[g2][2]);
            ffma2(z2[3], rr, w1p[g2][3]);
        }
        float4 zb = kd ? base1 : base0;
        float2 f0 = unpack2(z2[0]);
        float2 f1 = unpack2(z2[1]);
        float2 f2 = unpack2(z2[2]);
        float2 f3 = unpack2(z2[3]);
        float4 z;
        z.x = zb.x + b.x + f0.x + f0.y;
        z.y = zb.y + b.y + f1.x + f1.y;
        z.z = zb.z + b.z + f2.x + f2.y;
        z.w = zb.w + b.w + f3.x + f3.y;

        z.x = __fdividef(z.x, 1.f + __expf(-z.x));
        z.y = __fdividef(z.y, 1.f + __expf(-z.y));
        z.z = __fdividef(z.z, 1.f + __expf(-z.z));
        z.w = __fdividef(z.w, 1.f + __expf(-z.w));
        acc.x += z.x; acc.y += z.y; acc.z += z.z; acc.w += z.w;

        s = sn; d = dn; b = bn; abd = (i < 7) ? abdn : abd;
    }
    red_add_v4(g_aggY + (size_t)cur * 128 + 4 * lane, acc);
}

// ---------------- post: h = relu(h + aggY@W2 + deg*b2) (f32x2 packed) ----------------
// smem W2 stored k-pair interleaved: pos(k,c) = (k>>1)*128 + c*2 + (k&1)
__global__ void __launch_bounds__(256) k_post(const float* __restrict__ W2l,
                                              const float* __restrict__ b2l) {
    extern __shared__ float sm[];
    float* sW2 = sm;              // 64*128 = 8192 floats (interleaved)
    float* sY  = sm + 8192;       // [64][132]
    int t = threadIdx.x;
    int n0 = blockIdx.x * 64;

    for (int idx = t; idx < 128 * 64; idx += 256) {
        int k = idx >> 6, c = idx & 63;
        sW2[(k >> 1) * 128 + c * 2 + (k & 1)] = W2l[idx];
    }
    for (int idx = t; idx < 64 * 32; idx += 256) {
        int r = idx >> 5, q = idx & 31;
        int n = n0 + r;
        float4 v = (n < NN)
            ? *reinterpret_cast<const float4*>(g_aggY + (size_t)n * 128 + 4 * q)
            : make_float4(0.f, 0.f, 0.f, 0.f);
        *reinterpret_cast<float4*>(sY + r * 132 + 4 * q) = v;
    }
    __syncthreads();

    int tc = t & 15, tr = t >> 4;      // cols 4tc..4tc+3, nodes 4tr..4tr+3
    u64 acc2[4][4];
#pragma unroll
    for (int i = 0; i < 4; i++)
#pragma unroll
        for (int q = 0; q < 4; q++) acc2[i][q] = 0ULL;

    for (int k2 = 0; k2 < 64; k2 += 2) {
        const ulonglong2* wpa = reinterpret_cast<const ulonglong2*>(sW2 + (k2 + 0) * 128) + 2 * tc;
        const ulonglong2* wpb = reinterpret_cast<const ulonglong2*>(sW2 + (k2 + 1) * 128) + 2 * tc;
        ulonglong2 wa0 = wpa[0], wa1 = wpa[1];
        ulonglong2 wb0 = wpb[0], wb1 = wpb[1];
#pragma unroll
        for (int i = 0; i < 4; i++) {
            ulonglong2 yp = *reinterpret_cast<const ulonglong2*>(sY + (4 * tr + i) * 132 + 2 * k2);
            ffma2(acc2[i][0], wa0.x, yp.x);
            ffma2(acc2[i][1], wa0.y, yp.x);
            ffma2(acc2[i][2], wa1.x, yp.x);
            ffma2(acc2[i][3], wa1.y, yp.x);
            ffma2(acc2[i][0], wb0.x, yp.y);
            ffma2(acc2[i][1], wb0.y, yp.y);
            ffma2(acc2[i][2], wb1.x, yp.y);
            ffma2(acc2[i][3], wb1.y, yp.y);
        }
    }

    int c = tc * 4;
    float4 bb = *reinterpret_cast<const float4*>(b2l + c);
#pragma unroll
    for (int i = 0; i < 4; i++) {
        int n = n0 + 4 * tr + i;
        if (n < NN) {
            float2 f0 = unpack2(acc2[i][0]);
            float2 f1 = unpack2(acc2[i][1]);
            float2 f2 = unpack2(acc2[i][2]);
            float2 f3 = unpack2(acc2[i][3]);
            float dg = g_deg[n];
            float4 hv = *reinterpret_cast<const float4*>(g_h + (size_t)n * 64 + c);
            hv.x = fmaxf(hv.x + f0.x + f0.y + dg * bb.x, 0.f);
            hv.y = fmaxf(hv.y + f1.x + f1.y + dg * bb.y, 0.f);
            hv.z = fmaxf(hv.z + f2.x + f2.y + dg * bb.z, 0.f);
            hv.w = fmaxf(hv.w + f3.x + f3.y + dg * bb.w, 0.f);
            *reinterpret_cast<float4*>(g_h + (size_t)n * 64 + c) = hv;
        }
    }
}

// ---------------- mean pool (batch_ids sorted -> run accumulation) ----------------
__global__ void k_pool(const int* __restrict__ batch) {
    int t = threadIdx.x;
    int c = t & 63, r = t >> 6;
    int n0 = blockIdx.x * 128;
    float s = 0.f, cnt = 0.f;
    int bprev = -1;
    for (int it = 0; it < 32; it++) {
        int n = n0 + r + it * 4;
        if (n < NN) {
            int b = batch[n];
            if (b != bprev) {
                if (bprev >= 0) {
                    atomicAdd(&g_pool[bprev * 64 + c], s);
                    if (c == 0) atomicAdd(&g_cnt[bprev], cnt);
                }
                s = 0.f; cnt = 0.f; bprev = b;
            }
            s += g_h[(size_t)n * 64 + c];
            cnt += 1.f;
        }
    }
    if (bprev >= 0) {
        atomicAdd(&g_pool[bprev * 64 + c], s);
        if (c == 0) atomicAdd(&g_cnt[bprev], cnt);
    }
}
__global__ void k_final(const float* __restrict__ fcw, const float* __restrict__ fcb,
                        float* __restrict__ out) {
    int g = threadIdx.x;
    if (g >= NG) return;
    float cnt = fmaxf(g_cnt[g], 1.f);
    float s = 0.f;
    for (int j = 0; j < 64; j++) s += g_pool[g * 64 + j] * fcw[j];
    out[g] = s / cnt + fcb[0];
}

// ---------------- launch ----------------
extern "C" void kernel_launch(void* const* d_in, const int* in_sizes, int n_in,
                              void* d_out, int out_size) {
    const int*   atoms = (const int*)d_in[0];
    const int*   ei    = (const int*)d_in[1];
    const float* coord = (const float*)d_in[2];
    const int*   isr   = (const int*)d_in[3];
    const int*   batch = (const int*)d_in[4];
    const float* emb   = (const float*)d_in[5];
    const float* su    = (const float*)d_in[6];
    const float* W1    = (const float*)d_in[7];
    const float* b1    = (const float*)d_in[8];
    const float* W2    = (const float*)d_in[9];
    const float* b2    = (const float*)d_in[10];
    const float* fcw   = (const float*)d_in[11];
    const float* fcb   = (const float*)d_in[12];
    float* out = (float*)d_out;

    size_t smP = (size_t)(16384 + 32 * 64) * sizeof(float);
    size_t smQ = (size_t)(8192 + 64 * 132) * sizeof(float);
    cudaFuncSetAttribute(k_nodeproj, cudaFuncAttributeMaxDynamicSharedMemorySize, (int)smP);
    cudaFuncSetAttribute(k_post, cudaFuncAttributeMaxDynamicSharedMemorySize, (int)smQ);

    k_embed<<<(NN * 16 + 255) / 256, 256>>>(atoms, emb);
    k_zero_int<<<(NN + 255) / 256, 256>>>();
    k_count<<<(NE + 255) / 256, 256>>>(ei);
    k_scanA<<<SCAN_NB, SCAN_BLK>>>();
    k_scanB<<<1, 32>>>();
    k_scanC<<<(NN + 255) / 256, 256>>>();
    k_scatter<<<(NE + 255) / 256, 256>>>(ei, coord, isr);
    k_ktab_all<<<4, 128>>>(W1, b1, su);

    for (int l = 0; l < 4; l++) {
        const float* W1l = W1 + (size_t)l * CAT * H;
        k_nodeproj<<<NN / 32, 256, smP>>>(W1l);
        k_zeroY<<<(NN * 32 + 255) / 256, 256>>>();
        k_edge<<<NE / 64, 256>>>(W1l, l);
        k_post<<<(NN + 63) / 64, 256, smQ>>>(W2 + (size_t)l * H * D, b2 + l * D);
    }

    k_zero_pool<<<1, 1024>>>();
    k_pool<<<(NN + 127) / 128, 256>>>(batch);
    k_final<<<1, 64>>>(fcw, fcb, out);
}